// round 1
// baseline (speedup 1.0000x reference)
#include <cuda_runtime.h>

#define Bn 64
#define H  384
#define HH (H*H)
#define BORDER 3
#define CROP 378
#define NSH 49

// corr tiling
#define TX 128
#define TY 16
#define GX 3    // ceil(378/128)
#define GY 24   // ceil(378/16)
#define NTILE (GX*GY)   // 72
#define HALO_W 136      // need 134, pad to 136 (float4-safe, zero-filled)
#define HALO_H 22       // TY + 6

// scratch (static device memory; no allocations anywhere)
__device__ float g_part[Bn*NTILE*NSH*3];  // per-tile partials: hp, pp, mp
__device__ float g_box [Bn*NSH*3];        // Sm, SL, Shh per (batch,shift)
__device__ float g_sp  [Bn];              // Sum of pred per batch
__device__ float g_bmin[Bn];              // per-batch min cMSE

// ---------------------------------------------------------------------------
// Kernel 1b: box sums Sm(i,j), SL(i,j), Shh(i,j) per batch via row marginals,
// plus Sp = sum of pred over the center crop. One block per batch.
// ---------------------------------------------------------------------------
__global__ __launch_bounds__(384) void box_kernel(
    const float* __restrict__ sr, const float* __restrict__ hr,
    const float* __restrict__ mk)
{
    const int batch = blockIdx.x;
    const float* mb = mk + (size_t)batch*HH;
    const float* hb = hr + (size_t)batch*HH;
    const float* sb = sr + (size_t)batch*HH;

    __shared__ float wr[3][H][7];   // window row-sums per field
    __shared__ float rowp[H];
    __shared__ float coltot[3][7];

    const int tid  = threadIdx.x;
    const int w    = tid >> 5;
    const int lane = tid & 31;

    // 12 warps, each handles rows w, w+12, ... (32 rows). Coalesced x chunks.
    for (int y = w; y < H; y += 12) {
        float tm = 0.f, tmh = 0.f, tmh2 = 0.f, tp = 0.f;
        float fm[6], fmh[6], fmh2[6];   // x = 0..5
        float bm[6], bmh[6], bmh2[6];   // x = 378..383
        #pragma unroll
        for (int c = 0; c < 12; c++) {
            const int x = c*32 + lane;
            const float m  = mb[y*H + x];
            const float h  = hb[y*H + x];
            const float mh = m*h;
            const float mh2 = mh*h;
            tm += m; tmh += mh; tmh2 += mh2;
            if (x >= BORDER && x < H-BORDER && y >= BORDER && y < H-BORDER)
                tp += sb[y*H + x] * m;
            if (c == 0) {
                #pragma unroll
                for (int j = 0; j < 6; j++) {
                    fm[j]   = __shfl_sync(0xffffffffu, m,   j);
                    fmh[j]  = __shfl_sync(0xffffffffu, mh,  j);
                    fmh2[j] = __shfl_sync(0xffffffffu, mh2, j);
                }
            }
            if (c == 11) {
                #pragma unroll
                for (int j = 0; j < 6; j++) {
                    bm[j]   = __shfl_sync(0xffffffffu, m,   26+j);
                    bmh[j]  = __shfl_sync(0xffffffffu, mh,  26+j);
                    bmh2[j] = __shfl_sync(0xffffffffu, mh2, 26+j);
                }
            }
        }
        #pragma unroll
        for (int off = 16; off; off >>= 1) {
            tm   += __shfl_xor_sync(0xffffffffu, tm,   off);
            tmh  += __shfl_xor_sync(0xffffffffu, tmh,  off);
            tmh2 += __shfl_xor_sync(0xffffffffu, tmh2, off);
            tp   += __shfl_xor_sync(0xffffffffu, tp,   off);
        }
        if (lane == 0) {
            #pragma unroll
            for (int j = 0; j < 7; j++) {
                float lm = 0.f, lmh = 0.f, lmh2 = 0.f;
                float rm = 0.f, rmh = 0.f, rmh2 = 0.f;
                #pragma unroll
                for (int k = 0; k < 6; k++) {
                    if (k < j)  { lm += fm[k]; lmh += fmh[k]; lmh2 += fmh2[k]; }
                    if (k >= j) { rm += bm[k]; rmh += bmh[k]; rmh2 += bmh2[k]; }
                }
                wr[0][y][j] = tm   - lm   - rm;
                wr[1][y][j] = tmh  - lmh  - rmh;
                wr[2][y][j] = tmh2 - lmh2 - rmh2;
            }
            rowp[y] = tp;
        }
    }
    __syncthreads();

    if (tid < 21) {
        const int f = tid / 7, j = tid % 7;
        float s = 0.f;
        for (int y = 0; y < H; y++) s += wr[f][y][j];
        coltot[f][j] = s;
    }
    if (tid == 21) {
        float s = 0.f;
        for (int y = 0; y < H; y++) s += rowp[y];
        g_sp[batch] = s;
    }
    __syncthreads();

    if (tid < NSH) {
        const int i = tid / 7, j = tid % 7;
        #pragma unroll
        for (int f = 0; f < 3; f++) {
            float s = coltot[f][j];
            for (int y = 0; y < i; y++)        s -= wr[f][y][j];
            for (int y = i + CROP; y < H; y++) s -= wr[f][y][j];
            g_box[((size_t)batch*NSH + tid)*3 + f] = s;
        }
    }
}

// ---------------------------------------------------------------------------
// Kernel 1: the three 7x7 correlations Shp, Spp, Smp (tile partials).
// 7 warps per block; warp w owns shift-row i = w.
// ---------------------------------------------------------------------------
__global__ __launch_bounds__(224) void corr_kernel(
    const float* __restrict__ sr, const float* __restrict__ hr,
    const float* __restrict__ mk)
{
    __shared__ __align__(16) float s_m [HALO_H*HALO_W];
    __shared__ __align__(16) float s_mh[HALO_H*HALO_W];
    __shared__ __align__(16) float s_p [TY*TX];
    __shared__ __align__(16) float s_pp[TY*TX];

    const int batch = blockIdx.z;
    const int x0 = blockIdx.x * TX;
    const int y0 = blockIdx.y * TY;
    const float* mb = mk + (size_t)batch*HH;
    const float* hb = hr + (size_t)batch*HH;
    const float* sb = sr + (size_t)batch*HH;
    const int tid = threadIdx.x;

    // halo tile of m and m*h (zero-fill OOB / pad columns)
    for (int idx = tid; idx < HALO_H*HALO_W; idx += 224) {
        const int r = idx / HALO_W, c = idx % HALO_W;
        const int y = y0 + r, x = x0 + c;
        float m = 0.f, mh = 0.f;
        if (c < 134 && y < H && x < H) {
            m  = mb[y*H + x];
            mh = m * hb[y*H + x];
        }
        s_m[idx] = m; s_mh[idx] = mh;
    }
    // pred tile (p = 0 outside valid crop => no flow predicates needed later)
    for (int idx = tid; idx < TY*TX; idx += 224) {
        const int r = idx / TX, c = idx % TX;
        const int y = y0 + r, x = x0 + c;
        float p = 0.f;
        if (y < CROP && x < CROP)
            p = sb[(y+BORDER)*H + x+BORDER] * mb[(y+BORDER)*H + x+BORDER];
        s_p[idx] = p; s_pp[idx] = p*p;
    }
    __syncthreads();

    const int wid  = tid >> 5;      // shift row i = wid (0..6)
    const int lane = tid & 31;
    const int cb   = lane * 4;      // lane owns 4 consecutive output columns

    float a_hp[7], a_pp[7], a_mp[7];
    #pragma unroll
    for (int j = 0; j < 7; j++) { a_hp[j]=0.f; a_pp[j]=0.f; a_mp[j]=0.f; }

    for (int r = 0; r < TY; r++) {
        const float4 p4 = *(const float4*)&s_p [r*TX + cb];
        const float4 q4 = *(const float4*)&s_pp[r*TX + cb];
        const float pv[4] = {p4.x, p4.y, p4.z, p4.w};
        const float qv[4] = {q4.x, q4.y, q4.z, q4.w};

        const int hbase = (r + wid)*HALO_W + cb;
        float mw[12], hw[12];
        {
            float4 t;
            t = *(const float4*)&s_m[hbase];    mw[0]=t.x; mw[1]=t.y; mw[2]=t.z; mw[3]=t.w;
            t = *(const float4*)&s_m[hbase+4];  mw[4]=t.x; mw[5]=t.y; mw[6]=t.z; mw[7]=t.w;
            t = *(const float4*)&s_m[hbase+8];  mw[8]=t.x; mw[9]=t.y; mw[10]=t.z; mw[11]=t.w;
            t = *(const float4*)&s_mh[hbase];   hw[0]=t.x; hw[1]=t.y; hw[2]=t.z; hw[3]=t.w;
            t = *(const float4*)&s_mh[hbase+4]; hw[4]=t.x; hw[5]=t.y; hw[6]=t.z; hw[7]=t.w;
            t = *(const float4*)&s_mh[hbase+8]; hw[8]=t.x; hw[9]=t.y; hw[10]=t.z; hw[11]=t.w;
        }
        #pragma unroll
        for (int j = 0; j < 7; j++) {
            #pragma unroll
            for (int k = 0; k < 4; k++) {
                a_hp[j] = fmaf(hw[j+k], pv[k], a_hp[j]);
                a_mp[j] = fmaf(mw[j+k], pv[k], a_mp[j]);
                a_pp[j] = fmaf(mw[j+k], qv[k], a_pp[j]);
            }
        }
    }

    // warp reduce 21 accumulators
    #pragma unroll
    for (int j = 0; j < 7; j++) {
        #pragma unroll
        for (int off = 16; off; off >>= 1) {
            a_hp[j] += __shfl_xor_sync(0xffffffffu, a_hp[j], off);
            a_pp[j] += __shfl_xor_sync(0xffffffffu, a_pp[j], off);
            a_mp[j] += __shfl_xor_sync(0xffffffffu, a_mp[j], off);
        }
    }
    if (lane == 0) {
        const int tile = blockIdx.y*GX + blockIdx.x;
        float* out = g_part + ((size_t)(batch*NTILE + tile)*NSH + wid*7)*3;
        #pragma unroll
        for (int j = 0; j < 7; j++) {
            out[j*3 + 0] = a_hp[j];
            out[j*3 + 1] = a_pp[j];
            out[j*3 + 2] = a_mp[j];
        }
    }
}

// ---------------------------------------------------------------------------
// Kernel 2: per (batch,shift) mse from the six sums; min over shifts.
// ---------------------------------------------------------------------------
__global__ __launch_bounds__(64) void mse_kernel()
{
    const int b = blockIdx.x;
    const int s = threadIdx.x;   // 64 threads, 49 active
    __shared__ float smin[64];
    float mse = 3.4e38f;
    if (s < NSH) {
        float hp = 0.f, pp = 0.f, mp = 0.f;
        const float* base = g_part + ((size_t)b*NTILE*NSH + s)*3;
        for (int t = 0; t < NTILE; t++) {
            const float* q = base + (size_t)t*NSH*3;
            hp += q[0]; pp += q[1]; mp += q[2];
        }
        const float Sm  = g_box[((size_t)b*NSH + s)*3 + 0];
        const float SL  = g_box[((size_t)b*NSH + s)*3 + 1];
        const float Shh = g_box[((size_t)b*NSH + s)*3 + 2];
        const float Sp  = g_sp[b];
        const float bias = (SL - Sp) / Sm;
        const float num  = Shh - 2.f*hp + pp - 2.f*bias*(SL - mp) + bias*bias*Sm;
        mse = num / Sm;
    }
    smin[s] = mse;
    __syncthreads();
    #pragma unroll
    for (int off = 32; off; off >>= 1) {
        if (s < off) smin[s] = fminf(smin[s], smin[s + off]);
        __syncthreads();
    }
    if (s == 0) g_bmin[b] = smin[0];
}

// ---------------------------------------------------------------------------
// Kernel 3: mean over batches -> scalar output
// ---------------------------------------------------------------------------
__global__ __launch_bounds__(64) void final_kernel(float* __restrict__ out)
{
    __shared__ float sm[64];
    const int t = threadIdx.x;
    sm[t] = g_bmin[t];
    __syncthreads();
    #pragma unroll
    for (int off = 32; off; off >>= 1) {
        if (t < off) sm[t] += sm[t + off];
        __syncthreads();
    }
    if (t == 0) out[0] = sm[0] * (1.f / (float)Bn);
}

extern "C" void kernel_launch(void* const* d_in, const int* in_sizes, int n_in,
                              void* d_out, int out_size)
{
    const float* sr = (const float*)d_in[0];
    const float* hr = (const float*)d_in[1];
    const float* mk = (const float*)d_in[2];
    (void)in_sizes; (void)n_in; (void)out_size;

    box_kernel<<<Bn, 384>>>(sr, hr, mk);
    corr_kernel<<<dim3(GX, GY, Bn), 224>>>(sr, hr, mk);
    mse_kernel<<<Bn, 64>>>();
    final_kernel<<<1, 64>>>((float*)d_out);
}